// round 1
// baseline (speedup 1.0000x reference)
#include <cuda_runtime.h>

#define R  5
#define KW 11
#define BW 32
#define BH 8
#define TLW (BW + 2*R)   // 42
#define TLH (BH + 2*R)   // 18
#define H 256
#define W 256
#define CHW (H*W)

// c_i = -0.5 * (1/sigma_i) * log2(e), folded so weight = ex2(sum c_i * d_i^2)
#define CA (-0.07213475204444817f)   // sigma 10.0  (ch 0,1)
#define CB (-36.06737602222409f)     // sigma 0.02  (ch 2,3,4)
#define CC (-7.213475204444817f)     // sigma 0.1   (ch 5,6,7)

__device__ __forceinline__ float ex2f(float x) {
    float y;
    asm("ex2.approx.ftz.f32 %0, %1;" : "=f"(y) : "f"(x));
    return y;
}

__device__ __forceinline__ int refl(int i, int n) {
    if (i < 0)  i = -i;
    if (i >= n) i = 2*n - 2 - i;
    return i;
}

__global__ __launch_bounds__(256)
void jbf_kernel(const float* __restrict__ img,
                const float* __restrict__ gd,
                float* __restrict__ out)
{
    __shared__ float4 sg0[TLH][TLW];
    __shared__ float4 sg1[TLH][TLW];
    __shared__ float4 si [TLH][TLW];

    const int b   = blockIdx.z;
    const int tx0 = blockIdx.x * BW;
    const int ty0 = blockIdx.y * BH;

    const float* gb = gd  + (size_t)b * 8 * CHW;
    const float* ib = img + (size_t)b * 3 * CHW;

    const int tid = threadIdx.y * BW + threadIdx.x;

    // Cooperative halo load with reflect padding
    for (int i = tid; i < TLH * TLW; i += BW * BH) {
        int ly = i / TLW;
        int lx = i - ly * TLW;
        int gy = refl(ty0 + ly - R, H);
        int gx = refl(tx0 + lx - R, W);
        int off = gy * W + gx;
        sg0[ly][lx] = make_float4(gb[off],         gb[CHW   + off],
                                  gb[2*CHW + off], gb[3*CHW + off]);
        sg1[ly][lx] = make_float4(gb[4*CHW + off], gb[5*CHW + off],
                                  gb[6*CHW + off], gb[7*CHW + off]);
        si [ly][lx] = make_float4(ib[off], ib[CHW + off], ib[2*CHW + off], 0.0f);
    }
    __syncthreads();

    const int lx = threadIdx.x;
    const int ly = threadIdx.y;

    const float4 c0 = sg0[ly + R][lx + R];
    const float4 c1 = sg1[ly + R][lx + R];

    float wsum = 0.0f, ax = 0.0f, ay = 0.0f, az = 0.0f;

    for (int dy = 0; dy < KW; ++dy) {
        #pragma unroll
        for (int dx = 0; dx < KW; ++dx) {
            float4 g0 = sg0[ly + dy][lx + dx];
            float4 g1 = sg1[ly + dy][lx + dx];

            float d, m;
            d = g0.x - c0.x;  m = (CA * d) * d;
            d = g0.y - c0.y;  m = fmaf(CA * d, d, m);
            d = g0.z - c0.z;  m = fmaf(CB * d, d, m);
            d = g0.w - c0.w;  m = fmaf(CB * d, d, m);
            d = g1.x - c1.x;  m = fmaf(CB * d, d, m);
            d = g1.y - c1.y;  m = fmaf(CC * d, d, m);
            d = g1.z - c1.z;  m = fmaf(CC * d, d, m);
            d = g1.w - c1.w;  m = fmaf(CC * d, d, m);

            float w = ex2f(m);

            float4 p = si[ly + dy][lx + dx];
            ax = fmaf(w, p.x, ax);
            ay = fmaf(w, p.y, ay);
            az = fmaf(w, p.z, az);
            wsum += w;
        }
    }

    const float inv = 1.0f / wsum;
    const int oy = ty0 + ly;
    const int ox = tx0 + lx;
    float* ob = out + (size_t)b * 3 * CHW + oy * W + ox;
    ob[0]       = ax * inv;
    ob[CHW]     = ay * inv;
    ob[2*CHW]   = az * inv;
}

extern "C" void kernel_launch(void* const* d_in, const int* in_sizes, int n_in,
                              void* d_out, int out_size)
{
    const float* img = (const float*)d_in[0];   // (2,3,256,256)
    const float* gd  = (const float*)d_in[1];   // (2,8,256,256)
    float* out = (float*)d_out;                 // (2,3,256,256)

    dim3 block(BW, BH);
    dim3 grid(W / BW, H / BH, 2);
    jbf_kernel<<<grid, block>>>(img, gd, out);
}

// round 2
// speedup vs baseline: 1.1509x; 1.1509x over previous
#include <cuda_runtime.h>

#define R  5
#define KW 11
#define BW 32
#define BH 4
#define PY 2
#define TILE_H (BH*PY)        // 8
#define TLW (BW + 2*R)        // 42
#define TLH (TILE_H + 2*R)    // 18
#define H 256
#define W 256
#define CHW (H*W)

// c_i = -0.5 * (1/sigma_i) * log2(e), folded so weight = ex2(sum c_i * d_i^2)
#define CA (-0.07213475204444817f)   // sigma 10.0  (ch 0,1)
#define CB (-36.06737602222409f)     // sigma 0.02  (ch 2,3,4)
#define CC (-7.213475204444817f)     // sigma 0.1   (ch 5,6,7)

__device__ __forceinline__ float ex2f(float x) {
    float y;
    asm("ex2.approx.ftz.f32 %0, %1;" : "=f"(y) : "f"(x));
    return y;
}

__device__ __forceinline__ int refl(int i, int n) {
    if (i < 0)  i = -i;
    if (i >= n) i = 2*n - 2 - i;
    return i;
}

__device__ __forceinline__ float maha8(const float4 g0, const float4 g1,
                                       const float4 c0, const float4 c1) {
    float d, m;
    d = g0.x - c0.x;  m = (CA * d) * d;
    d = g0.y - c0.y;  m = fmaf(CA * d, d, m);
    d = g0.z - c0.z;  m = fmaf(CB * d, d, m);
    d = g0.w - c0.w;  m = fmaf(CB * d, d, m);
    d = g1.x - c1.x;  m = fmaf(CB * d, d, m);
    d = g1.y - c1.y;  m = fmaf(CC * d, d, m);
    d = g1.z - c1.z;  m = fmaf(CC * d, d, m);
    d = g1.w - c1.w;  m = fmaf(CC * d, d, m);
    return m;
}

__global__ __launch_bounds__(BW*BH)
void jbf_kernel(const float* __restrict__ img,
                const float* __restrict__ gd,
                float* __restrict__ out)
{
    __shared__ float4 sg0[TLH][TLW];
    __shared__ float4 sg1[TLH][TLW];
    __shared__ float4 si [TLH][TLW];

    const int b   = blockIdx.z;
    const int tx0 = blockIdx.x * BW;
    const int ty0 = blockIdx.y * TILE_H;

    const float* gb = gd  + (size_t)b * 8 * CHW;
    const float* ib = img + (size_t)b * 3 * CHW;

    const int tid = threadIdx.y * BW + threadIdx.x;

    // Cooperative halo load with reflect padding
    for (int i = tid; i < TLH * TLW; i += BW * BH) {
        int ly = i / TLW;
        int lx = i - ly * TLW;
        int gy = refl(ty0 + ly - R, H);
        int gx = refl(tx0 + lx - R, W);
        int off = gy * W + gx;
        sg0[ly][lx] = make_float4(gb[off],         gb[CHW   + off],
                                  gb[2*CHW + off], gb[3*CHW + off]);
        sg1[ly][lx] = make_float4(gb[4*CHW + off], gb[5*CHW + off],
                                  gb[6*CHW + off], gb[7*CHW + off]);
        si [ly][lx] = make_float4(ib[off], ib[CHW + off], ib[2*CHW + off], 0.0f);
    }
    __syncthreads();

    const int lx  = threadIdx.x;
    const int lyb = threadIdx.y * PY;   // tile row of pixel A; pixel B is lyb+1

    // Centers: pixel A at tile row lyb (smem row lyb+R), pixel B at lyb+1
    const float4 c0a = sg0[lyb + R    ][lx + R];
    const float4 c1a = sg1[lyb + R    ][lx + R];
    const float4 c0b = sg0[lyb + R + 1][lx + R];
    const float4 c1b = sg1[lyb + R + 1][lx + R];

    float wsA = 0.0f, axA = 0.0f, ayA = 0.0f, azA = 0.0f;
    float wsB = 0.0f, axB = 0.0f, ayB = 0.0f, azB = 0.0f;

    // e = 0: only pixel A (its dy = 0)
    {
        const float4* r0 = &sg0[lyb][lx];
        const float4* r1 = &sg1[lyb][lx];
        const float4* rp = &si [lyb][lx];
        #pragma unroll
        for (int dx = 0; dx < KW; ++dx) {
            float4 g0 = r0[dx], g1 = r1[dx], p = rp[dx];
            float w = ex2f(maha8(g0, g1, c0a, c1a));
            axA = fmaf(w, p.x, axA);
            ayA = fmaf(w, p.y, ayA);
            azA = fmaf(w, p.z, azA);
            wsA += w;
        }
    }

    // e = 1..10: both pixels share the loaded row
    for (int e = 1; e <= 10; ++e) {
        const float4* r0 = &sg0[lyb + e][lx];
        const float4* r1 = &sg1[lyb + e][lx];
        const float4* rp = &si [lyb + e][lx];
        #pragma unroll
        for (int dx = 0; dx < KW; ++dx) {
            float4 g0 = r0[dx], g1 = r1[dx], p = rp[dx];
            float wA = ex2f(maha8(g0, g1, c0a, c1a));
            float wB = ex2f(maha8(g0, g1, c0b, c1b));
            axA = fmaf(wA, p.x, axA);
            ayA = fmaf(wA, p.y, ayA);
            azA = fmaf(wA, p.z, azA);
            wsA += wA;
            axB = fmaf(wB, p.x, axB);
            ayB = fmaf(wB, p.y, ayB);
            azB = fmaf(wB, p.z, azB);
            wsB += wB;
        }
    }

    // e = 11: only pixel B (its dy = 10)
    {
        const float4* r0 = &sg0[lyb + 11][lx];
        const float4* r1 = &sg1[lyb + 11][lx];
        const float4* rp = &si [lyb + 11][lx];
        #pragma unroll
        for (int dx = 0; dx < KW; ++dx) {
            float4 g0 = r0[dx], g1 = r1[dx], p = rp[dx];
            float w = ex2f(maha8(g0, g1, c0b, c1b));
            axB = fmaf(w, p.x, axB);
            ayB = fmaf(w, p.y, ayB);
            azB = fmaf(w, p.z, azB);
            wsB += w;
        }
    }

    const int oy0 = ty0 + lyb;
    const int ox  = tx0 + lx;
    float* ob = out + (size_t)b * 3 * CHW + oy0 * W + ox;

    const float invA = 1.0f / wsA;
    ob[0]     = axA * invA;
    ob[CHW]   = ayA * invA;
    ob[2*CHW] = azA * invA;

    const float invB = 1.0f / wsB;
    ob[W]         = axB * invB;
    ob[CHW + W]   = ayB * invB;
    ob[2*CHW + W] = azB * invB;
}

extern "C" void kernel_launch(void* const* d_in, const int* in_sizes, int n_in,
                              void* d_out, int out_size)
{
    const float* img = (const float*)d_in[0];   // (2,3,256,256)
    const float* gd  = (const float*)d_in[1];   // (2,8,256,256)
    float* out = (float*)d_out;                 // (2,3,256,256)

    dim3 block(BW, BH);
    dim3 grid(W / BW, H / TILE_H, 2);
    jbf_kernel<<<grid, block>>>(img, gd, out);
}

// round 3
// speedup vs baseline: 1.3556x; 1.1778x over previous
#include <cuda_runtime.h>

#define R  5
#define KW 11
#define BW 32
#define TILE_H 8
#define PY 2
#define TLW (BW + 2*R)        // 42
#define TLH (TILE_H + 2*R)    // 18
#define H 256
#define W 256
#define CHW (H*W)

// c_i = -0.5 * (1/sigma_i) * log2(e), folded so weight = ex2(sum c_i * d_i^2)
#define CA (-0.07213475204444817f)   // sigma 10.0  (ch 0,1)
#define CB (-36.06737602222409f)     // sigma 0.02  (ch 2,3,4)
#define CC (-7.213475204444817f)     // sigma 0.1   (ch 5,6,7)

__device__ __forceinline__ float ex2f(float x) {
    float y;
    asm("ex2.approx.ftz.f32 %0, %1;" : "=f"(y) : "f"(x));
    return y;
}

__device__ __forceinline__ int refl(int i, int n) {
    if (i < 0)  i = -i;
    if (i >= n) i = 2*n - 2 - i;
    return i;
}

__device__ __forceinline__ float maha8(const float4 g0, const float4 g1,
                                       const float4 c0, const float4 c1) {
    float d, m;
    d = g0.x - c0.x;  m = (CA * d) * d;
    d = g0.y - c0.y;  m = fmaf(CA * d, d, m);
    d = g0.z - c0.z;  m = fmaf(CB * d, d, m);
    d = g0.w - c0.w;  m = fmaf(CB * d, d, m);
    d = g1.x - c1.x;  m = fmaf(CB * d, d, m);
    d = g1.y - c1.y;  m = fmaf(CC * d, d, m);
    d = g1.z - c1.z;  m = fmaf(CC * d, d, m);
    d = g1.w - c1.w;  m = fmaf(CC * d, d, m);
    return m;
}

__global__ __launch_bounds__(256, 3)
void jbf_kernel(const float* __restrict__ img,
                const float* __restrict__ gd,
                float* __restrict__ out)
{
    __shared__ float4 sg0[TLH][TLW];
    __shared__ float4 sg1[TLH][TLW];
    __shared__ float4 si [TLH][TLW];
    __shared__ float4 redA[4][BW];
    __shared__ float4 redB[4][BW];

    const int b   = blockIdx.z;
    const int tx0 = blockIdx.x * BW;
    const int ty0 = blockIdx.y * TILE_H;

    const float* gb = gd  + (size_t)b * 8 * CHW;
    const float* ib = img + (size_t)b * 3 * CHW;

    const int tid = threadIdx.y * BW + threadIdx.x;

    // Cooperative halo load with reflect padding (256 threads)
    for (int i = tid; i < TLH * TLW; i += 256) {
        int ly = i / TLW;
        int lxx = i - ly * TLW;
        int gy = refl(ty0 + ly - R, H);
        int gx = refl(tx0 + lxx - R, W);
        int off = gy * W + gx;
        sg0[ly][lxx] = make_float4(gb[off],         gb[CHW   + off],
                                   gb[2*CHW + off], gb[3*CHW + off]);
        sg1[ly][lxx] = make_float4(gb[4*CHW + off], gb[5*CHW + off],
                                   gb[6*CHW + off], gb[7*CHW + off]);
        si [ly][lxx] = make_float4(ib[off], ib[CHW + off], ib[2*CHW + off], 0.0f);
    }
    __syncthreads();

    const int lx   = threadIdx.x;
    const int ty   = threadIdx.y;     // 0..7
    const int half = ty >> 2;         // 0: e in 0..5,  1: e in 6..11
    const int g    = ty & 3;          // pixel-pair group 0..3
    const int lyb  = g * PY;          // tile row of pixel A; B = lyb+1

    const float4 c0a = sg0[lyb + R    ][lx + R];
    const float4 c1a = sg1[lyb + R    ][lx + R];
    const float4 c0b = sg0[lyb + R + 1][lx + R];
    const float4 c1b = sg1[lyb + R + 1][lx + R];

    // Incremental Mahalanobis constants: delta = cA - cB
    const float q0 = c0a.x - c0b.x, q1 = c0a.y - c0b.y;
    const float q2 = c0a.z - c0b.z, q3 = c0a.w - c0b.w;
    const float q4 = c1a.x - c1b.x, q5 = c1a.y - c1b.y;
    const float q6 = c1a.z - c1b.z, q7 = c1a.w - c1b.w;
    const float e0 = 2.0f*CA*q0, e1 = 2.0f*CA*q1;
    const float e2 = 2.0f*CB*q2, e3 = 2.0f*CB*q3, e4 = 2.0f*CB*q4;
    const float e5 = 2.0f*CC*q5, e6 = 2.0f*CC*q6, e7 = 2.0f*CC*q7;
    float Kc;
    Kc =      (CA*q0)*q0;
    Kc = fmaf( CA*q1, q1, Kc);
    Kc = fmaf( CB*q2, q2, Kc);
    Kc = fmaf( CB*q3, q3, Kc);
    Kc = fmaf( CB*q4, q4, Kc);
    Kc = fmaf( CC*q5, q5, Kc);
    Kc = fmaf( CC*q6, q6, Kc);
    Kc = fmaf( CC*q7, q7, Kc);

    float wsA = 0.0f, axA = 0.0f, ayA = 0.0f, azA = 0.0f;
    float wsB = 0.0f, axB = 0.0f, ayB = 0.0f, azB = 0.0f;

    // Dual rows: 5 per half (half0: e=1..5, half1: e=6..10)
    const int ebase = half ? 6 : 1;
    #pragma unroll 1
    for (int k = 0; k < 5; ++k) {
        const int e = ebase + k;
        const float4* r0 = &sg0[lyb + e][lx];
        const float4* r1 = &sg1[lyb + e][lx];
        const float4* rp = &si [lyb + e][lx];
        #pragma unroll
        for (int dx = 0; dx < KW; ++dx) {
            float4 g0 = r0[dx], g1 = r1[dx], p = rp[dx];

            float d0 = g0.x - c0a.x, d1 = g0.y - c0a.y;
            float d2 = g0.z - c0a.z, d3 = g0.w - c0a.w;
            float d4 = g1.x - c1a.x, d5 = g1.y - c1a.y;
            float d6 = g1.z - c1a.z, d7 = g1.w - c1a.w;

            float mA;
            mA =      (CA*d0)*d0;
            mA = fmaf( CA*d1, d1, mA);
            mA = fmaf( CB*d2, d2, mA);
            mA = fmaf( CB*d3, d3, mA);
            mA = fmaf( CB*d4, d4, mA);
            mA = fmaf( CC*d5, d5, mA);
            mA = fmaf( CC*d6, d6, mA);
            mA = fmaf( CC*d7, d7, mA);

            float t;
            t = fmaf(e0, d0, Kc);
            t = fmaf(e1, d1, t);
            t = fmaf(e2, d2, t);
            t = fmaf(e3, d3, t);
            t = fmaf(e4, d4, t);
            t = fmaf(e5, d5, t);
            t = fmaf(e6, d6, t);
            t = fmaf(e7, d7, t);
            float mB = mA + t;

            float wA = ex2f(mA);
            float wB = ex2f(mB);

            axA = fmaf(wA, p.x, axA);
            ayA = fmaf(wA, p.y, ayA);
            azA = fmaf(wA, p.z, azA);
            wsA += wA;
            axB = fmaf(wB, p.x, axB);
            ayB = fmaf(wB, p.y, ayB);
            azB = fmaf(wB, p.z, azB);
            wsB += wB;
        }
    }

    // Single rows: half0 does e=0 (pixel A only), half1 does e=11 (pixel B only)
    if (half == 0) {
        const float4* r0 = &sg0[lyb][lx];
        const float4* r1 = &sg1[lyb][lx];
        const float4* rp = &si [lyb][lx];
        #pragma unroll
        for (int dx = 0; dx < KW; ++dx) {
            float4 g0 = r0[dx], g1 = r1[dx], p = rp[dx];
            float w = ex2f(maha8(g0, g1, c0a, c1a));
            axA = fmaf(w, p.x, axA);
            ayA = fmaf(w, p.y, ayA);
            azA = fmaf(w, p.z, azA);
            wsA += w;
        }
    } else {
        const float4* r0 = &sg0[lyb + 11][lx];
        const float4* r1 = &sg1[lyb + 11][lx];
        const float4* rp = &si [lyb + 11][lx];
        #pragma unroll
        for (int dx = 0; dx < KW; ++dx) {
            float4 g0 = r0[dx], g1 = r1[dx], p = rp[dx];
            float w = ex2f(maha8(g0, g1, c0b, c1b));
            axB = fmaf(w, p.x, axB);
            ayB = fmaf(w, p.y, ayB);
            azB = fmaf(w, p.z, azB);
            wsB += w;
        }
    }

    __syncthreads();
    if (half == 1) {
        redA[g][lx] = make_float4(axA, ayA, azA, wsA);
        redB[g][lx] = make_float4(axB, ayB, azB, wsB);
    }
    __syncthreads();

    if (half == 0) {
        float4 rA = redA[g][lx];
        float4 rB = redB[g][lx];
        axA += rA.x; ayA += rA.y; azA += rA.z; wsA += rA.w;
        axB += rB.x; ayB += rB.y; azB += rB.z; wsB += rB.w;

        const int oy0 = ty0 + lyb;
        const int ox  = tx0 + lx;
        float* ob = out + (size_t)b * 3 * CHW + oy0 * W + ox;

        const float invA = 1.0f / wsA;
        ob[0]     = axA * invA;
        ob[CHW]   = ayA * invA;
        ob[2*CHW] = azA * invA;

        const float invB = 1.0f / wsB;
        ob[W]         = axB * invB;
        ob[CHW + W]   = ayB * invB;
        ob[2*CHW + W] = azB * invB;
    }
}

extern "C" void kernel_launch(void* const* d_in, const int* in_sizes, int n_in,
                              void* d_out, int out_size)
{
    const float* img = (const float*)d_in[0];   // (2,3,256,256)
    const float* gd  = (const float*)d_in[1];   // (2,8,256,256)
    float* out = (float*)d_out;                 // (2,3,256,256)

    dim3 block(BW, 8);
    dim3 grid(W / BW, H / TILE_H, 2);
    jbf_kernel<<<grid, block>>>(img, gd, out);
}